// round 14
// baseline (speedup 1.0000x reference)
#include <cuda_runtime.h>
#include <cuda_bf16.h>
#include <math.h>
#include <cstdint>

// Problem constants
#define BATCH 4
#define C 128
#define NG 8
#define CPG 16
#define NTOK 4096
#define EPS 1e-5f
#define QSCALE (0.08838834764831845f * 1.4426950408889634f)  // 1/sqrt(C) * log2(e)

// Scratch
__device__ float2        g_part[BATCH * NG * 16];     // partial (sum, sumsq)
__device__ unsigned char g_kv[BATCH * 64 * 32768];    // swizzled 32KB K/V tiles
__device__ unsigned int  g_flag[BATCH];               // per-batch barrier

// ---------------------------------------------------------------------------
// helpers
// ---------------------------------------------------------------------------
__device__ __forceinline__ void mma_bf16(float* d, const uint32_t* a,
                                         uint32_t b0, uint32_t b1) {
    asm volatile(
        "mma.sync.aligned.m16n8k16.row.col.f32.bf16.bf16.f32 "
        "{%0,%1,%2,%3}, {%4,%5,%6,%7}, {%8,%9}, {%0,%1,%2,%3};"
        : "+f"(d[0]), "+f"(d[1]), "+f"(d[2]), "+f"(d[3])
        : "r"(a[0]), "r"(a[1]), "r"(a[2]), "r"(a[3]), "r"(b0), "r"(b1));
}
#define LDSM4(R, A) \
    asm volatile("ldmatrix.sync.aligned.m8n8.x4.shared.b16 {%0,%1,%2,%3}, [%4];" \
        : "=r"((R)[0]), "=r"((R)[1]), "=r"((R)[2]), "=r"((R)[3]) : "r"(A))
#define LDSM4T(R, A) \
    asm volatile("ldmatrix.sync.aligned.m8n8.x4.trans.shared.b16 {%0,%1,%2,%3}, [%4];" \
        : "=r"((R)[0]), "=r"((R)[1]), "=r"((R)[2]), "=r"((R)[3]) : "r"(A))
__device__ __forceinline__ uint32_t pack_bf2(float a, float b) {
    __nv_bfloat162 h = __floats2bfloat162_rn(a, b);
    return *reinterpret_cast<uint32_t*>(&h);
}
__device__ __forceinline__ float ex2f(float x) {
    float r;
    asm("ex2.approx.f32 %0, %1;" : "=f"(r) : "f"(x));
    return r;
}
__device__ __forceinline__ void bulkcp(uint32_t dst, const void* src,
                                       uint32_t bytes, uint32_t mbar) {
    asm volatile(
        "cp.async.bulk.shared::cta.global.mbarrier::complete_tx::bytes "
        "[%0], [%1], %2, [%3];"
        :: "r"(dst), "l"(src), "r"(bytes), "r"(mbar) : "memory");
}
#define MBAR_INIT(a, n) \
    asm volatile("mbarrier.init.shared.b64 [%0], %1;" :: "r"(a), "r"(n) : "memory")
#define MBAR_EXPECT_TX(a, n) \
    asm volatile("mbarrier.arrive.expect_tx.shared.b64 _, [%0], %1;" \
                 :: "r"(a), "r"(n) : "memory")
#define MBAR_WAIT(addr, parity) do { \
    asm volatile("{\n\t.reg .pred P1;\n\t" \
        "WAIT_%=:\n\t" \
        "mbarrier.try_wait.parity.acquire.cta.shared::cta.b64 P1, [%0], %1, 0x989680;\n\t" \
        "@P1 bra.uni DONE_%=;\n\t" \
        "bra.uni WAIT_%=;\n\t" \
        "DONE_%=:\n\t}" \
        :: "r"(addr), "r"(parity) : "memory"); \
} while (0)

// ---------------------------------------------------------------------------
// Kernel 1: GroupNorm partial stats + barrier-flag reset. Grid 512.
// ---------------------------------------------------------------------------
__global__ void gn_stats_kernel(const float* __restrict__ x)
{
    if (blockIdx.x < BATCH && threadIdx.x == 0) g_flag[blockIdx.x] = 0;

    int bg = blockIdx.x >> 4, ck = blockIdx.x & 15;
    const float4* xp = (const float4*)(x + (size_t)bg * CPG * NTOK
                                         + (size_t)ck * (CPG * NTOK / 16));
    int t = threadIdx.x;
    float s = 0.f, ss = 0.f;
#pragma unroll
    for (int i = 0; i < 4; i++) {
        float4 v = xp[t + i * 256];
        s  += v.x + v.y + v.z + v.w;
        ss += v.x * v.x + v.y * v.y + v.z * v.z + v.w * v.w;
    }
#pragma unroll
    for (int o = 16; o > 0; o >>= 1) {
        s  += __shfl_xor_sync(0xffffffffu, s, o);
        ss += __shfl_xor_sync(0xffffffffu, ss, o);
    }
    __shared__ float rs[8], rss[8];
    if ((t & 31) == 0) { rs[t >> 5] = s; rss[t >> 5] = ss; }
    __syncthreads();
    if (t == 0) {
        float a = 0.f, b = 0.f;
#pragma unroll
        for (int i = 0; i < 8; i++) { a += rs[i]; b += rss[i]; }
        g_part[blockIdx.x] = make_float2(a, b);
    }
}

// ---------------------------------------------------------------------------
// Kernel 2: MEGA kernel, TQ=64, 2 CTAs/SM, key-split warps.
// Phase 1: GN-normalize + QKV (Q stays in smem; K/V -> swizzled g_kv tile).
// Barrier (64 CTAs/batch). Phase 2: flash attn (bulk-copy, 3 stages) +
// partial-O merge + fused proj + residual.
// Grid (64 q-tiles, 4 batches) = 256 CTAs, all co-resident.
// ---------------------------------------------------------------------------
#define QP 136
#define AP 72
#define TQ 64
#define TKEY 64
#define QBYTES (TQ * QP * 2)               // 17408
#define STB 32768
#define ST_OFF(s) (QBYTES + (s) * STB)     // 17408 / 50176 / 82944
#define AS_B 17408
#define BS_B 35840
#define OM_B 17408                         // merge buffer (fp32, pitch 132)
#define PF_B 17408                         // proj result (fp32, pitch 68)
#define WS_B 55296                         // W_proj bf16 (pitch 136)
#define MB_OFF 115712
#define LS_OFF 115776
#define MEGA_SMEM (LS_OFF + 256)           // 116032 B -> 2 CTAs/SM
#define OMP 132
#define PFP 68

__global__ __launch_bounds__(256, 2) void mega_kernel(const float* __restrict__ x,
                                                      const float* __restrict__ gnw,
                                                      const float* __restrict__ gnb,
                                                      const float* __restrict__ W,
                                                      const float* __restrict__ bias,
                                                      const float* __restrict__ pw,
                                                      const float* __restrict__ pb,
                                                      float* __restrict__ y)
{
    extern __shared__ char sbc[];
    __nv_bfloat16* sb = (__nv_bfloat16*)sbc;
    const uint32_t sbase = (uint32_t)__cvta_generic_to_shared(sbc);
    const int tid = threadIdx.x;
    const int w = tid >> 5, lane = tid & 31;
    const int gid = lane >> 2, tig = lane & 3;
    const int wq = w & 3;                    // q sub-tile (16 rows)
    const int grp = w >> 2;                  // key-half / o-half group
    const int kh = grp << 5;
    const int qrow = wq * 16 + gid;          // local q row (0..63)
    const int b = blockIdx.y;
    const int n0 = blockIdx.x * TQ;
    const uint32_t mbar = sbase + MB_OFF;

    // ============ PHASE 1: GroupNorm-normalize + QKV GEMM ============
    __shared__ float stats[16];
    if (tid < 8) {
        float s = 0.f, ss = 0.f;
#pragma unroll
        for (int ck = 0; ck < 16; ck++) {
            float2 p = g_part[(b * NG + tid) * 16 + ck];
            s += p.x; ss += p.y;
        }
        float mean = s * (1.f / (CPG * NTOK));
        float var  = ss * (1.f / (CPG * NTOK)) - mean * mean;
        stats[tid * 2]     = mean;
        stats[tid * 2 + 1] = rsqrtf(var + EPS);
    }
    __syncthreads();

    // As c-major [c:128][m:64] pitch AP, normalized bf16 (x read once)
    __nv_bfloat16* As = (__nv_bfloat16*)(sbc + AS_B);
    for (int i = tid; i < 128 * 16; i += 256) {
        int c = i >> 4, n4 = (i & 15) << 2;
        float4 v = *(const float4*)(x + ((size_t)b * C + c) * NTOK + n0 + n4);
        int g = c >> 4;
        float a = stats[g * 2 + 1] * gnw[c];
        float bb = gnb[c] - stats[g * 2] * a;
        *(uint32_t*)(As + c * AP + n4)     = pack_bf2(v.x * a + bb, v.y * a + bb);
        *(uint32_t*)(As + c * AP + n4 + 2) = pack_bf2(v.z * a + bb, v.w * a + bb);
    }

    const int l15 = lane & 15;
    const int hi8 = (lane >> 4) << 3;
    const int arow = (lane & 7) + ((lane >> 4) << 3);
    const int acol = ((lane >> 3) & 1) << 3;
    const uint32_t aA = sbase + AS_B + (arow * AP + wq * 16 + acol) * 2;
    __nv_bfloat16* Bs = (__nv_bfloat16*)(sbc + BS_B);
    const uint32_t aB = sbase + BS_B + ((grp * 64 + l15) * QP + hi8) * 2;
    unsigned char* dstb = g_kv + (size_t)b * (64 * 32768);

    const int obs[3] = {1, 2, 0};            // K, V, Q (Q stays resident)
#pragma unroll 1
    for (int oi = 0; oi < 3; oi++) {
        const int ob = obs[oi];
        const int o0 = ob * 128;
        for (int i = tid; i < 128 * 32; i += 256) {
            int r = i >> 5, c4 = (i & 31) << 2;
            float4 v = *(const float4*)(W + (size_t)(o0 + r) * C + c4);
            *(uint32_t*)(Bs + r * QP + c4)     = pack_bf2(v.x, v.y);
            *(uint32_t*)(Bs + r * QP + c4 + 2) = pack_bf2(v.z, v.w);
        }
        __syncthreads();

        float acc[8][4];
#pragma unroll
        for (int i = 0; i < 8; i++)
#pragma unroll
            for (int j = 0; j < 4; j++) acc[i][j] = 0.f;

#pragma unroll
        for (int kk = 0; kk < 8; kk++) {
            const int k0 = kk * 16;
            uint32_t aq[4];
            LDSM4T(aq, aA + k0 * AP * 2);
#pragma unroll
            for (int ntp = 0; ntp < 4; ntp++) {
                uint32_t bk[4];
                LDSM4(bk, aB + (ntp * 16 * QP + k0) * 2);
                mma_bf16(acc[2 * ntp],     aq, bk[0], bk[2]);
                mma_bf16(acc[2 * ntp + 1], aq, bk[1], bk[3]);
            }
        }
        __syncthreads();

        // stage bf16 [m:64][o:128] into Q region
        const float sc = (ob == 0) ? QSCALE : 1.f;
#pragma unroll
        for (int nt = 0; nt < 8; nt++) {
            int o = grp * 64 + nt * 8 + 2 * tig;
            float b0 = bias[o0 + o], b1 = bias[o0 + o + 1];
            *(uint32_t*)(sb + qrow * QP + o) =
                pack_bf2((acc[nt][0] + b0) * sc, (acc[nt][1] + b1) * sc);
            *(uint32_t*)(sb + (qrow + 8) * QP + o) =
                pack_bf2((acc[nt][2] + b0) * sc, (acc[nt][3] + b1) * sc);
        }
        __syncthreads();

        if (ob != 0) {
            // this CTA's 64 tokens == KV tile jt = blockIdx.x
            const int kv = ob - 1;
            for (int i = tid; i < 64 * 16; i += 256) {
                int rl = i >> 4, ch = i & 15;
                int sub = ch >> 3;
                uint32_t off = (uint32_t)blockIdx.x * 32768u + (uint32_t)kv * 16384u
                             + (uint32_t)sub * 8192u + (uint32_t)rl * 128u
                             + ((((uint32_t)rl & 7u) * 16u) ^ (((uint32_t)ch & 7u) * 16u));
                *(uint4*)(dstb + off) = *(const uint4*)(sb + rl * QP + ch * 8);
            }
            __syncthreads();
        }
    }

    if (tid == 0) {
        MBAR_INIT(mbar + 0, 1);
        MBAR_INIT(mbar + 8, 1);
        MBAR_INIT(mbar + 16, 1);
    }
    __syncthreads();

    // ============ per-batch global barrier (64 CTAs) ============
    if (tid == 0) {
        asm volatile("red.release.gpu.global.add.u32 [%0], 1;"
                     :: "l"(&g_flag[b]) : "memory");
        unsigned v;
        do {
            asm volatile("ld.acquire.gpu.global.u32 %0, [%1];"
                         : "=r"(v) : "l"(&g_flag[b]) : "memory");
        } while (v < 64);
    }
    __syncthreads();
    asm volatile("fence.proxy.async;" ::: "memory");

    // ============ PHASE 2: flash attention (key-split) ============
    const unsigned char* KVg = dstb;
    if (tid == 0) {
        MBAR_EXPECT_TX(mbar + 0, STB);
        bulkcp(sbase + ST_OFF(0), KVg, STB, mbar + 0);
        MBAR_EXPECT_TX(mbar + 8, STB);
        bulkcp(sbase + ST_OFF(1), KVg + STB, STB, mbar + 8);
    }

    const uint32_t aQ = sbase + ((wq * 16 + l15) * QP + hi8) * 2;
    const int vrow = (lane & 7) + ((lane >> 3) & 1) * 8;

    float oacc[16][4];
#pragma unroll
    for (int i = 0; i < 16; i++)
#pragma unroll
        for (int j = 0; j < 4; j++) oacc[i][j] = 0.f;
    float l0 = 0.f, l1 = 0.f;

    const int NT = NTOK / TKEY;
    for (int jt = 0; jt < NT; jt++) {
        const int s = jt % 3;
        MBAR_WAIT(mbar + 8 * s, (jt / 3) & 1);
        __syncthreads();
        if (jt + 2 < NT && tid == 0) {
            const int s2 = (jt + 2) % 3;
            MBAR_EXPECT_TX(mbar + 8 * s2, STB);
            bulkcp(sbase + ST_OFF(s2), KVg + (size_t)(jt + 2) * STB, STB,
                   mbar + 8 * s2);
        }

        const uint32_t stK = sbase + ST_OFF(s);
        const uint32_t stV = stK + 16384;

        // ---- S = Q K^T for this warp's 32-key half ----
        float sacc[4][4];
#pragma unroll
        for (int i = 0; i < 4; i++)
#pragma unroll
            for (int j = 0; j < 4; j++) sacc[i][j] = 0.f;

#pragma unroll
        for (int kk = 0; kk < 8; kk++) {
            const int k0 = kk * 16;
            uint32_t aq[4];
            LDSM4(aq, aQ + k0 * 2);
            const uint32_t sub = (k0 >= 64) ? 8192u : 0u;
            const uint32_t colb = (uint32_t)(((k0 & 63) + hi8) * 2);
#pragma unroll
            for (int ntp = 0; ntp < 2; ntp++) {
                const uint32_t row = (uint32_t)(kh + ntp * 16 + l15);
                uint32_t bk[4];
                LDSM4(bk, stK + sub + row * 128u + (((row & 7u) * 16u) ^ colb));
                mma_bf16(sacc[2 * ntp],     aq, bk[0], bk[2]);
                mma_bf16(sacc[2 * ntp + 1], aq, bk[1], bk[3]);
            }
        }

        // ---- softmax (ex2) + O-MMA over the 32-key half ----
#pragma unroll
        for (int kk = 0; kk < 2; kk++) {
            uint32_t ap[4];
            {
                float p0 = ex2f(sacc[2 * kk][0]);
                float p1 = ex2f(sacc[2 * kk][1]);
                float p2 = ex2f(sacc[2 * kk][2]);
                float p3 = ex2f(sacc[2 * kk][3]);
                l0 += p0 + p1; l1 += p2 + p3;
                ap[0] = pack_bf2(p0, p1);
                ap[1] = pack_bf2(p2, p3);
                float q0 = ex2f(sacc[2 * kk + 1][0]);
                float q1 = ex2f(sacc[2 * kk + 1][1]);
                float q2 = ex2f(sacc[2 * kk + 1][2]);
                float q3 = ex2f(sacc[2 * kk + 1][3]);
                l0 += q0 + q1; l1 += q2 + q3;
                ap[2] = pack_bf2(q0, q1);
                ap[3] = pack_bf2(q2, q3);
            }
            const uint32_t rowb = (uint32_t)(kh + kk * 16 + vrow);
            const uint32_t rxor = (rowb & 7u) * 16u;
#pragma unroll
            for (int ccp = 0; ccp < 8; ccp++) {
                const int cc = ccp * 16 + hi8;
                const uint32_t sub = (cc >= 64) ? 8192u : 0u;
                const uint32_t colb = (uint32_t)((cc & 63) * 2);
                uint32_t bv[4];
                LDSM4T(bv, stV + sub + rowb * 128u + (rxor ^ colb));
                mma_bf16(oacc[2 * ccp],     ap, bv[0], bv[1]);
                mma_bf16(oacc[2 * ccp + 1], ap, bv[2], bv[3]);
            }
        }
    }
    __syncthreads();   // all stages consumed

    // ---- merge key-halves: quad-reduce l, grp0 dumps, grp1 merges ----
    l0 += __shfl_xor_sync(0xffffffffu, l0, 1);
    l0 += __shfl_xor_sync(0xffffffffu, l0, 2);
    l1 += __shfl_xor_sync(0xffffffffu, l1, 1);
    l1 += __shfl_xor_sync(0xffffffffu, l1, 2);

    float* Om   = (float*)(sbc + OM_B);
    float* lsum = (float*)(sbc + LS_OFF);
    if (grp == 0) {
#pragma unroll
        for (int nt = 0; nt < 16; nt++) {
            int col = nt * 8 + 2 * tig;
            Om[qrow * OMP + col]           = oacc[nt][0];
            Om[qrow * OMP + col + 1]       = oacc[nt][1];
            Om[(qrow + 8) * OMP + col]     = oacc[nt][2];
            Om[(qrow + 8) * OMP + col + 1] = oacc[nt][3];
        }
        if (tig == 0) { lsum[qrow] = l0; lsum[qrow + 8] = l1; }
    }
    // W_proj load (all threads) overlaps grp0's dump
    __nv_bfloat16* Ws = (__nv_bfloat16*)(sbc + WS_B);
    for (int i = tid; i < 128 * 32; i += 256) {
        int r = i >> 5, c4 = (i & 31) << 2;
        float4 v = *(const float4*)(pw + (size_t)r * C + c4);
        *(uint32_t*)(Ws + r * QP + c4)     = pack_bf2(v.x, v.y);
        *(uint32_t*)(Ws + r * QP + c4 + 2) = pack_bf2(v.z, v.w);
    }
    __syncthreads();

    if (grp == 1) {
        float inv0 = 1.f / (l0 + lsum[qrow]);
        float inv1 = 1.f / (l1 + lsum[qrow + 8]);
#pragma unroll
        for (int nt = 0; nt < 16; nt++) {
            int col = nt * 8 + 2 * tig;
            float o0 = (Om[qrow * OMP + col]           + oacc[nt][0]) * inv0;
            float o1 = (Om[qrow * OMP + col + 1]       + oacc[nt][1]) * inv0;
            float o2 = (Om[(qrow + 8) * OMP + col]     + oacc[nt][2]) * inv1;
            float o3 = (Om[(qrow + 8) * OMP + col + 1] + oacc[nt][3]) * inv1;
            *(uint32_t*)(sb + qrow * QP + col)       = pack_bf2(o0, o1);
            *(uint32_t*)(sb + (qrow + 8) * QP + col) = pack_bf2(o2, o3);
        }
    }
    __syncthreads();

    // ---- fused proj: warp does 16q x 64o ----
    const uint32_t aW = sbase + WS_B + ((grp * 64 + l15) * QP + hi8) * 2;

    float acc[8][4];
#pragma unroll
    for (int i = 0; i < 8; i++)
#pragma unroll
        for (int j = 0; j < 4; j++) acc[i][j] = 0.f;

#pragma unroll
    for (int kk = 0; kk < 8; kk++) {
        const int k0 = kk * 16;
        uint32_t aq[4];
        LDSM4(aq, aQ + k0 * 2);            // O lives in Q region
#pragma unroll
        for (int ntp = 0; ntp < 4; ntp++) {
            uint32_t bk[4];
            LDSM4(bk, aW + (ntp * 16 * QP + k0) * 2);
            mma_bf16(acc[2 * ntp],     aq, bk[0], bk[2]);
            mma_bf16(acc[2 * ntp + 1], aq, bk[1], bk[3]);
        }
    }
    __syncthreads();   // Om reads done; merge buffer reusable

    // ---- stage proj fp32 [o:128][n:64] ----
    float* Pf = (float*)(sbc + PF_B);
    const int nl = wq * 16 + gid;
#pragma unroll
    for (int nt = 0; nt < 8; nt++) {
        int o = grp * 64 + nt * 8 + 2 * tig;
        Pf[o * PFP + nl]           = acc[nt][0];
        Pf[(o + 1) * PFP + nl]     = acc[nt][1];
        Pf[o * PFP + nl + 8]       = acc[nt][2];
        Pf[(o + 1) * PFP + nl + 8] = acc[nt][3];
    }
    __syncthreads();

    // ---- coalesced residual add + store ----
    for (int i = tid; i < 128 * 16; i += 256) {
        int o = i >> 4, n4 = (i & 15) << 2;
        size_t gaddr = ((size_t)b * C + o) * NTOK + n0 + n4;
        float4 xv = *(const float4*)(x + gaddr);
        float4 ov = *(const float4*)(Pf + o * PFP + n4);
        float bo = pb[o];
        float4 r = make_float4(xv.x + ov.x + bo, xv.y + ov.y + bo,
                               xv.z + ov.z + bo, xv.w + ov.w + bo);
        *(float4*)(y + gaddr) = r;
    }
}

// ---------------------------------------------------------------------------
extern "C" void kernel_launch(void* const* d_in, const int* in_sizes, int n_in,
                              void* d_out, int out_size)
{
    const float* x     = (const float*)d_in[0];
    const float* gn_w  = (const float*)d_in[1];
    const float* gn_b  = (const float*)d_in[2];
    const float* qkv_w = (const float*)d_in[3];
    const float* qkv_b = (const float*)d_in[4];
    const float* pr_w  = (const float*)d_in[5];
    const float* pr_b  = (const float*)d_in[6];
    float* y = (float*)d_out;

    cudaFuncSetAttribute(mega_kernel, cudaFuncAttributeMaxDynamicSharedMemorySize,
                         MEGA_SMEM);

    gn_stats_kernel<<<BATCH * NG * 16, 256>>>(x);
    mega_kernel<<<dim3(NTOK / TQ, BATCH), 256, MEGA_SMEM>>>(
        x, gn_w, gn_b, qkv_w, qkv_b, pr_w, pr_b, y);
}

// round 15
// speedup vs baseline: 1.1868x; 1.1868x over previous
#include <cuda_runtime.h>
#include <cuda_bf16.h>
#include <math.h>
#include <cstdint>

// Problem constants
#define BATCH 4
#define C 128
#define NG 8
#define CPG 16
#define NTOK 4096
#define EPS 1e-5f
#define QSCALE (0.08838834764831845f * 1.4426950408889634f)  // 1/sqrt(C) * log2(e)

// Scratch
__device__ float2        g_part[BATCH * NG * 16];     // partial (sum, sumsq)
__device__ unsigned char g_kv[BATCH * 64 * 32768];    // swizzled 32KB K/V tiles
__device__ unsigned int  g_flag[BATCH];               // per-batch barrier

// ---------------------------------------------------------------------------
// helpers
// ---------------------------------------------------------------------------
__device__ __forceinline__ void mma_bf16(float* d, const uint32_t* a,
                                         uint32_t b0, uint32_t b1) {
    asm volatile(
        "mma.sync.aligned.m16n8k16.row.col.f32.bf16.bf16.f32 "
        "{%0,%1,%2,%3}, {%4,%5,%6,%7}, {%8,%9}, {%0,%1,%2,%3};"
        : "+f"(d[0]), "+f"(d[1]), "+f"(d[2]), "+f"(d[3])
        : "r"(a[0]), "r"(a[1]), "r"(a[2]), "r"(a[3]), "r"(b0), "r"(b1));
}
#define LDSM4(R, A) \
    asm volatile("ldmatrix.sync.aligned.m8n8.x4.shared.b16 {%0,%1,%2,%3}, [%4];" \
        : "=r"((R)[0]), "=r"((R)[1]), "=r"((R)[2]), "=r"((R)[3]) : "r"(A))
#define LDSM4T(R, A) \
    asm volatile("ldmatrix.sync.aligned.m8n8.x4.trans.shared.b16 {%0,%1,%2,%3}, [%4];" \
        : "=r"((R)[0]), "=r"((R)[1]), "=r"((R)[2]), "=r"((R)[3]) : "r"(A))
__device__ __forceinline__ uint32_t pack_bf2(float a, float b) {
    __nv_bfloat162 h = __floats2bfloat162_rn(a, b);
    return *reinterpret_cast<uint32_t*>(&h);
}
__device__ __forceinline__ float ex2f(float x) {
    float r;
    asm("ex2.approx.f32 %0, %1;" : "=f"(r) : "f"(x));
    return r;
}
__device__ __forceinline__ void bulkcp(uint32_t dst, const void* src,
                                       uint32_t bytes, uint32_t mbar) {
    asm volatile(
        "cp.async.bulk.shared::cta.global.mbarrier::complete_tx::bytes "
        "[%0], [%1], %2, [%3];"
        :: "r"(dst), "l"(src), "r"(bytes), "r"(mbar) : "memory");
}
#define MBAR_INIT(a, n) \
    asm volatile("mbarrier.init.shared.b64 [%0], %1;" :: "r"(a), "r"(n) : "memory")
#define MBAR_EXPECT_TX(a, n) \
    asm volatile("mbarrier.arrive.expect_tx.shared.b64 _, [%0], %1;" \
                 :: "r"(a), "r"(n) : "memory")
#define MBAR_WAIT(addr, parity) do { \
    asm volatile("{\n\t.reg .pred P1;\n\t" \
        "WAIT_%=:\n\t" \
        "mbarrier.try_wait.parity.acquire.cta.shared::cta.b64 P1, [%0], %1, 0x989680;\n\t" \
        "@P1 bra.uni DONE_%=;\n\t" \
        "bra.uni WAIT_%=;\n\t" \
        "DONE_%=:\n\t}" \
        :: "r"(addr), "r"(parity) : "memory"); \
} while (0)

// ---------------------------------------------------------------------------
// Kernel 1: GroupNorm partial stats + barrier-flag reset. Grid 512.
// ---------------------------------------------------------------------------
__global__ void gn_stats_kernel(const float* __restrict__ x)
{
    if (blockIdx.x < BATCH && threadIdx.x == 0) g_flag[blockIdx.x] = 0;

    int bg = blockIdx.x >> 4, ck = blockIdx.x & 15;
    const float4* xp = (const float4*)(x + (size_t)bg * CPG * NTOK
                                         + (size_t)ck * (CPG * NTOK / 16));
    int t = threadIdx.x;
    float s = 0.f, ss = 0.f;
#pragma unroll
    for (int i = 0; i < 4; i++) {
        float4 v = xp[t + i * 256];
        s  += v.x + v.y + v.z + v.w;
        ss += v.x * v.x + v.y * v.y + v.z * v.z + v.w * v.w;
    }
#pragma unroll
    for (int o = 16; o > 0; o >>= 1) {
        s  += __shfl_xor_sync(0xffffffffu, s, o);
        ss += __shfl_xor_sync(0xffffffffu, ss, o);
    }
    __shared__ float rs[8], rss[8];
    if ((t & 31) == 0) { rs[t >> 5] = s; rss[t >> 5] = ss; }
    __syncthreads();
    if (t == 0) {
        float a = 0.f, b = 0.f;
#pragma unroll
        for (int i = 0; i < 8; i++) { a += rs[i]; b += rss[i]; }
        g_part[blockIdx.x] = make_float2(a, b);
    }
}

// ---------------------------------------------------------------------------
// Kernel 2: MEGA kernel, 512 threads (16 warps), TQ=128, 1 CTA/SM.
// Phase 2 uses key-split warp groups (8 q-subtiles x 2 key-halves) with an
// intra-CTA partial-O merge. Bulk-copy 3-stage KV ring. Fused proj+residual.
// Grid (32 q-tiles, 4 batches) = 128 CTAs, 1 wave, all co-resident.
// ---------------------------------------------------------------------------
#define THREADS 512
#define GP 136
#define QP 136
#define TQ 128
#define TKEY 64
#define QBYTES (TQ * QP * 2)               // 34816
#define STB 32768
#define ST_OFF(s) (QBYTES + (s) * STB)     // 34816 / 67584 / 100352
#define WB_OFF (QBYTES + 3 * STB)          // 133120 (As ph1 / W_proj ph2)
#define MB_OFF (WB_OFF + 128 * GP * 2)     // 167936
#define LS_OFF (MB_OFF + 64)               // 168000 (128 floats)
#define MEGA_SMEM (LS_OFF + 512)           // 168512 B
#define OMP 132                            // fp32 merge/proj pitch

__global__ __launch_bounds__(THREADS, 1) void mega_kernel(const float* __restrict__ x,
                                                          const float* __restrict__ gnw,
                                                          const float* __restrict__ gnb,
                                                          const float* __restrict__ W,
                                                          const float* __restrict__ bias,
                                                          const float* __restrict__ pw,
                                                          const float* __restrict__ pb,
                                                          float* __restrict__ y)
{
    extern __shared__ char sbc[];
    __nv_bfloat16* sb = (__nv_bfloat16*)sbc;
    const uint32_t sbase = (uint32_t)__cvta_generic_to_shared(sbc);
    const int tid = threadIdx.x;
    const int w = tid >> 5, lane = tid & 31;
    const int gid = lane >> 2, tig = lane & 3;
    const int wq = w & 7;                    // q sub-tile (16 rows)
    const int grp = w >> 3;                  // key-half / o-half group
    const int kh = grp << 5;
    const int qrow = wq * 16 + gid;          // local q row (0..127)
    const int b = blockIdx.y;
    const int n0 = blockIdx.x * TQ;
    const uint32_t mbar = sbase + MB_OFF;

    // ============ PHASE 1: GroupNorm-normalize + QKV GEMM ============
    __shared__ float stats[16];
    if (tid < 8) {
        float s = 0.f, ss = 0.f;
#pragma unroll
        for (int ck = 0; ck < 16; ck++) {
            float2 p = g_part[(b * NG + tid) * 16 + ck];
            s += p.x; ss += p.y;
        }
        float mean = s * (1.f / (CPG * NTOK));
        float var  = ss * (1.f / (CPG * NTOK)) - mean * mean;
        stats[tid * 2]     = mean;
        stats[tid * 2 + 1] = rsqrtf(var + EPS);
    }
    __syncthreads();

    // As c-major [c:128][m:128] pitch GP in WB region (x read once)
    __nv_bfloat16* As = (__nv_bfloat16*)(sbc + WB_OFF);
    for (int i = tid; i < 128 * 32; i += THREADS) {
        int c = i >> 5, n4 = (i & 31) << 2;
        float4 v = *(const float4*)(x + ((size_t)b * C + c) * NTOK + n0 + n4);
        int g = c >> 4;
        float a = stats[g * 2 + 1] * gnw[c];
        float bb = gnb[c] - stats[g * 2] * a;
        *(uint32_t*)(As + c * GP + n4)     = pack_bf2(v.x * a + bb, v.y * a + bb);
        *(uint32_t*)(As + c * GP + n4 + 2) = pack_bf2(v.z * a + bb, v.w * a + bb);
    }

    const int l15 = lane & 15;
    const int hi8 = (lane >> 4) << 3;
    const int arow = (lane & 7) + ((lane >> 4) << 3);
    const int acol = ((lane >> 3) & 1) << 3;
    const uint32_t aA = sbase + WB_OFF + (arow * GP + wq * 16 + acol) * 2;
    __nv_bfloat16* Bs = (__nv_bfloat16*)(sbc + ST_OFF(0));   // spans stage0+1
    const uint32_t aB = sbase + ST_OFF(0) + ((grp * 64 + l15) * GP + hi8) * 2;
    unsigned char* dstb = g_kv + (size_t)b * (64 * 32768);

    const int obs[3] = {1, 2, 0};            // K, V, Q (Q stays resident)
#pragma unroll 1
    for (int oi = 0; oi < 3; oi++) {
        const int ob = obs[oi];
        const int o0 = ob * 128;
        for (int i = tid; i < 128 * 32; i += THREADS) {
            int r = i >> 5, c4 = (i & 31) << 2;
            float4 v = *(const float4*)(W + (size_t)(o0 + r) * C + c4);
            *(uint32_t*)(Bs + r * GP + c4)     = pack_bf2(v.x, v.y);
            *(uint32_t*)(Bs + r * GP + c4 + 2) = pack_bf2(v.z, v.w);
        }
        __syncthreads();

        float acc[8][4];
#pragma unroll
        for (int i = 0; i < 8; i++)
#pragma unroll
            for (int j = 0; j < 4; j++) acc[i][j] = 0.f;

#pragma unroll
        for (int kk = 0; kk < 8; kk++) {
            const int k0 = kk * 16;
            uint32_t aq[4];
            LDSM4T(aq, aA + k0 * GP * 2);
#pragma unroll
            for (int ntp = 0; ntp < 4; ntp++) {
                uint32_t bk[4];
                LDSM4(bk, aB + (ntp * 16 * GP + k0) * 2);
                mma_bf16(acc[2 * ntp],     aq, bk[0], bk[2]);
                mma_bf16(acc[2 * ntp + 1], aq, bk[1], bk[3]);
            }
        }
        __syncthreads();

        // stage bf16 [m:128][o:128] into Q region
        const float sc = (ob == 0) ? QSCALE : 1.f;
#pragma unroll
        for (int nt = 0; nt < 8; nt++) {
            int o = grp * 64 + nt * 8 + 2 * tig;
            float b0 = bias[o0 + o], b1 = bias[o0 + o + 1];
            *(uint32_t*)(sb + qrow * QP + o) =
                pack_bf2((acc[nt][0] + b0) * sc, (acc[nt][1] + b1) * sc);
            *(uint32_t*)(sb + (qrow + 8) * QP + o) =
                pack_bf2((acc[nt][2] + b0) * sc, (acc[nt][3] + b1) * sc);
        }
        __syncthreads();

        if (ob != 0) {
            // coalesced swizzled K/V tile write (2 tiles per CTA)
            const int kv = ob - 1;
            for (int i = tid; i < 128 * 16; i += THREADS) {
                int r = i >> 4, ch = i & 15;
                int nl = n0 + r;
                int jt = nl >> 6, rl = nl & 63;
                int sub = ch >> 3;
                uint32_t off = (uint32_t)jt * 32768u + (uint32_t)kv * 16384u
                             + (uint32_t)sub * 8192u + (uint32_t)rl * 128u
                             + ((((uint32_t)rl & 7u) * 16u) ^ (((uint32_t)ch & 7u) * 16u));
                *(uint4*)(dstb + off) = *(const uint4*)(sb + r * QP + ch * 8);
            }
            __syncthreads();
        }
    }

    // load W_proj into WB (As retired); init mbarriers
    __nv_bfloat16* Ws = (__nv_bfloat16*)(sbc + WB_OFF);
    for (int i = tid; i < 128 * 32; i += THREADS) {
        int r = i >> 5, c4 = (i & 31) << 2;
        float4 v = *(const float4*)(pw + (size_t)r * C + c4);
        *(uint32_t*)(Ws + r * GP + c4)     = pack_bf2(v.x, v.y);
        *(uint32_t*)(Ws + r * GP + c4 + 2) = pack_bf2(v.z, v.w);
    }
    if (tid == 0) {
        MBAR_INIT(mbar + 0, 1);
        MBAR_INIT(mbar + 8, 1);
        MBAR_INIT(mbar + 16, 1);
    }
    __syncthreads();

    // ============ per-batch global barrier (32 CTAs) ============
    if (tid == 0) {
        asm volatile("red.release.gpu.global.add.u32 [%0], 1;"
                     :: "l"(&g_flag[b]) : "memory");
        unsigned v;
        do {
            asm volatile("ld.acquire.gpu.global.u32 %0, [%1];"
                         : "=r"(v) : "l"(&g_flag[b]) : "memory");
        } while (v < 32);
    }
    __syncthreads();
    asm volatile("fence.proxy.async;" ::: "memory");

    // ============ PHASE 2: flash attention (key-split, 16 warps) ============
    const unsigned char* KVg = dstb;
    if (tid == 0) {
        MBAR_EXPECT_TX(mbar + 0, STB);
        bulkcp(sbase + ST_OFF(0), KVg, STB, mbar + 0);
        MBAR_EXPECT_TX(mbar + 8, STB);
        bulkcp(sbase + ST_OFF(1), KVg + STB, STB, mbar + 8);
    }

    const uint32_t aQ = sbase + ((wq * 16 + l15) * QP + hi8) * 2;
    const int vrow = (lane & 7) + ((lane >> 3) & 1) * 8;

    float oacc[16][4];
#pragma unroll
    for (int i = 0; i < 16; i++)
#pragma unroll
        for (int j = 0; j < 4; j++) oacc[i][j] = 0.f;
    float l0 = 0.f, l1 = 0.f;

    const int NT = NTOK / TKEY;
    for (int jt = 0; jt < NT; jt++) {
        const int s = jt % 3;
        MBAR_WAIT(mbar + 8 * s, (jt / 3) & 1);
        __syncthreads();
        if (jt + 2 < NT && tid == 0) {
            const int s2 = (jt + 2) % 3;
            MBAR_EXPECT_TX(mbar + 8 * s2, STB);
            bulkcp(sbase + ST_OFF(s2), KVg + (size_t)(jt + 2) * STB, STB,
                   mbar + 8 * s2);
        }

        const uint32_t stK = sbase + ST_OFF(s);
        const uint32_t stV = stK + 16384;

        // ---- S = Q K^T for this warp's 32-key half ----
        float sacc[4][4];
#pragma unroll
        for (int i = 0; i < 4; i++)
#pragma unroll
            for (int j = 0; j < 4; j++) sacc[i][j] = 0.f;

#pragma unroll
        for (int kk = 0; kk < 8; kk++) {
            const int k0 = kk * 16;
            uint32_t aq[4];
            LDSM4(aq, aQ + k0 * 2);
            const uint32_t sub = (k0 >= 64) ? 8192u : 0u;
            const uint32_t colb = (uint32_t)(((k0 & 63) + hi8) * 2);
#pragma unroll
            for (int ntp = 0; ntp < 2; ntp++) {
                const uint32_t row = (uint32_t)(kh + ntp * 16 + l15);
                uint32_t bk[4];
                LDSM4(bk, stK + sub + row * 128u + (((row & 7u) * 16u) ^ colb));
                mma_bf16(sacc[2 * ntp],     aq, bk[0], bk[2]);
                mma_bf16(sacc[2 * ntp + 1], aq, bk[1], bk[3]);
            }
        }

        // ---- softmax (ex2) + O-MMA over the 32-key half ----
#pragma unroll
        for (int kk = 0; kk < 2; kk++) {
            uint32_t ap[4];
            {
                float p0 = ex2f(sacc[2 * kk][0]);
                float p1 = ex2f(sacc[2 * kk][1]);
                float p2 = ex2f(sacc[2 * kk][2]);
                float p3 = ex2f(sacc[2 * kk][3]);
                l0 += p0 + p1; l1 += p2 + p3;
                ap[0] = pack_bf2(p0, p1);
                ap[1] = pack_bf2(p2, p3);
                float q0 = ex2f(sacc[2 * kk + 1][0]);
                float q1 = ex2f(sacc[2 * kk + 1][1]);
                float q2 = ex2f(sacc[2 * kk + 1][2]);
                float q3 = ex2f(sacc[2 * kk + 1][3]);
                l0 += q0 + q1; l1 += q2 + q3;
                ap[2] = pack_bf2(q0, q1);
                ap[3] = pack_bf2(q2, q3);
            }
            const uint32_t rowb = (uint32_t)(kh + kk * 16 + vrow);
            const uint32_t rxor = (rowb & 7u) * 16u;
#pragma unroll
            for (int ccp = 0; ccp < 8; ccp++) {
                const int cc = ccp * 16 + hi8;
                const uint32_t sub = (cc >= 64) ? 8192u : 0u;
                const uint32_t colb = (uint32_t)((cc & 63) * 2);
                uint32_t bv[4];
                LDSM4T(bv, stV + sub + rowb * 128u + (rxor ^ colb));
                mma_bf16(oacc[2 * ccp],     ap, bv[0], bv[1]);
                mma_bf16(oacc[2 * ccp + 1], ap, bv[2], bv[3]);
            }
        }
    }
    __syncthreads();   // all stages consumed

    // ---- merge key-halves (intra-CTA): quad-reduce l, grp0 dumps ----
    l0 += __shfl_xor_sync(0xffffffffu, l0, 1);
    l0 += __shfl_xor_sync(0xffffffffu, l0, 2);
    l1 += __shfl_xor_sync(0xffffffffu, l1, 1);
    l1 += __shfl_xor_sync(0xffffffffu, l1, 2);

    float* Om   = (float*)(sbc + ST_OFF(0));   // [q:128][c:128] pitch OMP
    float* lsum = (float*)(sbc + LS_OFF);
    if (grp == 0) {
#pragma unroll
        for (int nt = 0; nt < 16; nt++) {
            int col = nt * 8 + 2 * tig;
            Om[qrow * OMP + col]           = oacc[nt][0];
            Om[qrow * OMP + col + 1]       = oacc[nt][1];
            Om[(qrow + 8) * OMP + col]     = oacc[nt][2];
            Om[(qrow + 8) * OMP + col + 1] = oacc[nt][3];
        }
        if (tig == 0) { lsum[qrow] = l0; lsum[qrow + 8] = l1; }
    }
    __syncthreads();

    // grp1 merges, normalizes, writes bf16 O into Q region
    if (grp == 1) {
        float inv0 = 1.f / (l0 + lsum[qrow]);
        float inv1 = 1.f / (l1 + lsum[qrow + 8]);
#pragma unroll
        for (int nt = 0; nt < 16; nt++) {
            int col = nt * 8 + 2 * tig;
            float o0 = (Om[qrow * OMP + col]           + oacc[nt][0]) * inv0;
            float o1 = (Om[qrow * OMP + col + 1]       + oacc[nt][1]) * inv0;
            float o2 = (Om[(qrow + 8) * OMP + col]     + oacc[nt][2]) * inv1;
            float o3 = (Om[(qrow + 8) * OMP + col + 1] + oacc[nt][3]) * inv1;
            *(uint32_t*)(sb + qrow * QP + col)       = pack_bf2(o0, o1);
            *(uint32_t*)(sb + (qrow + 8) * QP + col) = pack_bf2(o2, o3);
        }
    }
    __syncthreads();

    // ---- fused proj: warp does 16q x 64o ----
    const uint32_t aW = sbase + WB_OFF + ((grp * 64 + l15) * GP + hi8) * 2;

    float acc[8][4];
#pragma unroll
    for (int i = 0; i < 8; i++)
#pragma unroll
        for (int j = 0; j < 4; j++) acc[i][j] = 0.f;

#pragma unroll
    for (int kk = 0; kk < 8; kk++) {
        const int k0 = kk * 16;
        uint32_t aq[4];
        LDSM4(aq, aQ + k0 * 2);            // O lives in Q region
#pragma unroll
        for (int ntp = 0; ntp < 4; ntp++) {
            uint32_t bk[4];
            LDSM4(bk, aW + (ntp * 16 * GP + k0) * 2);
            mma_bf16(acc[2 * ntp],     aq, bk[0], bk[2]);
            mma_bf16(acc[2 * ntp + 1], aq, bk[1], bk[3]);
        }
    }
    __syncthreads();   // Om reads done; stage region reusable

    // ---- stage proj fp32 [o:128][n:128] pitch OMP ----
    float* Pf = (float*)(sbc + ST_OFF(0));
    const int nl = wq * 16 + gid;
#pragma unroll
    for (int nt = 0; nt < 8; nt++) {
        int o = grp * 64 + nt * 8 + 2 * tig;
        Pf[o * OMP + nl]           = acc[nt][0];
        Pf[(o + 1) * OMP + nl]     = acc[nt][1];
        Pf[o * OMP + nl + 8]       = acc[nt][2];
        Pf[(o + 1) * OMP + nl + 8] = acc[nt][3];
    }
    __syncthreads();

    // ---- coalesced residual add + store ----
    for (int i = tid; i < 128 * 32; i += THREADS) {
        int o = i >> 5, n4 = (i & 31) << 2;
        size_t gaddr = ((size_t)b * C + o) * NTOK + n0 + n4;
        float4 xv = *(const float4*)(x + gaddr);
        float4 ov = *(const float4*)(Pf + o * OMP + n4);
        float bo = pb[o];
        float4 r = make_float4(xv.x + ov.x + bo, xv.y + ov.y + bo,
                               xv.z + ov.z + bo, xv.w + ov.w + bo);
        *(float4*)(y + gaddr) = r;
    }
}

// ---------------------------------------------------------------------------
extern "C" void kernel_launch(void* const* d_in, const int* in_sizes, int n_in,
                              void* d_out, int out_size)
{
    const float* x     = (const float*)d_in[0];
    const float* gn_w  = (const float*)d_in[1];
    const float* gn_b  = (const float*)d_in[2];
    const float* qkv_w = (const float*)d_in[3];
    const float* qkv_b = (const float*)d_in[4];
    const float* pr_w  = (const float*)d_in[5];
    const float* pr_b  = (const float*)d_in[6];
    float* y = (float*)d_out;

    cudaFuncSetAttribute(mega_kernel, cudaFuncAttributeMaxDynamicSharedMemorySize,
                         MEGA_SMEM);

    gn_stats_kernel<<<BATCH * NG * 16, 256>>>(x);
    mega_kernel<<<dim3(NTOK / TQ, BATCH), THREADS, MEGA_SMEM>>>(
        x, gn_w, gn_b, qkv_w, qkv_b, pr_w, pr_b, y);
}

// round 17
// speedup vs baseline: 1.2728x; 1.0725x over previous
#include <cuda_runtime.h>
#include <cuda_bf16.h>
#include <math.h>
#include <cstdint>

// Problem constants
#define BATCH 4
#define C 128
#define NG 8
#define CPG 16
#define NTOK 4096
#define EPS 1e-5f
#define QSCALE (0.08838834764831845f * 1.4426950408889634f)  // 1/sqrt(C) * log2(e)

// Scratch
__device__ float2        g_part[BATCH * NG * 32];     // per-CTA partial stats
__device__ unsigned char g_kv[BATCH * 64 * 32768];    // swizzled 32KB K/V tiles
__device__ unsigned int  g_flag[8];                   // [0..3]=stats bar, [4..7]=kv bar

// ---------------------------------------------------------------------------
// helpers
// ---------------------------------------------------------------------------
__device__ __forceinline__ void mma_bf16(float* d, const uint32_t* a,
                                         uint32_t b0, uint32_t b1) {
    asm volatile(
        "mma.sync.aligned.m16n8k16.row.col.f32.bf16.bf16.f32 "
        "{%0,%1,%2,%3}, {%4,%5,%6,%7}, {%8,%9}, {%0,%1,%2,%3};"
        : "+f"(d[0]), "+f"(d[1]), "+f"(d[2]), "+f"(d[3])
        : "r"(a[0]), "r"(a[1]), "r"(a[2]), "r"(a[3]), "r"(b0), "r"(b1));
}
#define LDSM4(R, A) \
    asm volatile("ldmatrix.sync.aligned.m8n8.x4.shared.b16 {%0,%1,%2,%3}, [%4];" \
        : "=r"((R)[0]), "=r"((R)[1]), "=r"((R)[2]), "=r"((R)[3]) : "r"(A))
#define LDSM4T(R, A) \
    asm volatile("ldmatrix.sync.aligned.m8n8.x4.trans.shared.b16 {%0,%1,%2,%3}, [%4];" \
        : "=r"((R)[0]), "=r"((R)[1]), "=r"((R)[2]), "=r"((R)[3]) : "r"(A))
__device__ __forceinline__ uint32_t pack_bf2(float a, float b) {
    __nv_bfloat162 h = __floats2bfloat162_rn(a, b);
    return *reinterpret_cast<uint32_t*>(&h);
}
__device__ __forceinline__ float ex2f(float x) {
    float r;
    asm("ex2.approx.f32 %0, %1;" : "=f"(r) : "f"(x));
    return r;
}
__device__ __forceinline__ void bulkcp(uint32_t dst, const void* src,
                                       uint32_t bytes, uint32_t mbar) {
    asm volatile(
        "cp.async.bulk.shared::cta.global.mbarrier::complete_tx::bytes "
        "[%0], [%1], %2, [%3];"
        :: "r"(dst), "l"(src), "r"(bytes), "r"(mbar) : "memory");
}
#define MBAR_INIT(a, n) \
    asm volatile("mbarrier.init.shared.b64 [%0], %1;" :: "r"(a), "r"(n) : "memory")
#define MBAR_EXPECT_TX(a, n) \
    asm volatile("mbarrier.arrive.expect_tx.shared.b64 _, [%0], %1;" \
                 :: "r"(a), "r"(n) : "memory")
#define MBAR_ARRIVE(a) \
    asm volatile("mbarrier.arrive.shared.b64 _, [%0];" :: "r"(a) : "memory")
#define MBAR_WAIT(addr, parity) do { \
    asm volatile("{\n\t.reg .pred P1;\n\t" \
        "WAIT_%=:\n\t" \
        "mbarrier.try_wait.parity.acquire.cta.shared::cta.b64 P1, [%0], %1, 0x989680;\n\t" \
        "@P1 bra.uni DONE_%=;\n\t" \
        "bra.uni WAIT_%=;\n\t" \
        "DONE_%=:\n\t}" \
        :: "r"(addr), "r"(parity) : "memory"); \
} while (0)

// ---------------------------------------------------------------------------
// MEGA kernel, 512 threads (16 warps), TQ=128, 1 CTA/SM, grid (32, 4).
// Phase 0: x -> smem fp32 + GN stats (global barrier A).
// Phase 1: GN-normalize + QKV GEMM (Q resident; K/V -> swizzled g_kv).
// Global barrier B. Phase 2: decoupled-pipeline flash attention (bulk-copy,
// full/free mbarriers, NO per-tile CTA sync) + merge + fused proj + residual.
// ---------------------------------------------------------------------------
#define THREADS 512
#define GP 136
#define QP 136
#define TQ 128
#define TKEY 64
#define QBYTES (TQ * QP * 2)               // 34816
#define STB 32768
#define ST_OFF(s) (QBYTES + (s) * STB)     // 34816 / 67584 / 100352
#define WB_OFF (QBYTES + 3 * STB)          // 133120 (As ph1 / W_proj ph2)
#define MB_OFF (WB_OFF + 128 * GP * 2)     // 167936 (6 mbarriers, 48B)
#define LS_OFF (MB_OFF + 64)               // 168000
#define MEGA_SMEM (LS_OFF + 512)           // 168512 B
#define OMP 132                            // fp32 merge/proj pitch

__global__ __launch_bounds__(THREADS, 1) void mega_kernel(const float* __restrict__ x,
                                                          const float* __restrict__ gnw,
                                                          const float* __restrict__ gnb,
                                                          const float* __restrict__ W,
                                                          const float* __restrict__ bias,
                                                          const float* __restrict__ pw,
                                                          const float* __restrict__ pb,
                                                          float* __restrict__ y)
{
    extern __shared__ char sbc[];
    __nv_bfloat16* sb = (__nv_bfloat16*)sbc;
    const uint32_t sbase = (uint32_t)__cvta_generic_to_shared(sbc);
    const int tid = threadIdx.x;
    const int w = tid >> 5, lane = tid & 31;
    const int gid = lane >> 2, tig = lane & 3;
    const int wq = w & 7;                    // q sub-tile (16 rows)
    const int grp = w >> 3;                  // key-half / o-half group
    const int kh = grp << 5;
    const int qrow = wq * 16 + gid;          // local q row (0..127)
    const int b = blockIdx.y;
    const int n0 = blockIdx.x * TQ;
    const uint32_t mbar = sbase + MB_OFF;

    // ============ PHASE 0: x -> smem + GroupNorm stats ============
    float* Xs = (float*)(sbc + ST_OFF(0));   // [c:128][n:128] fp32, 64KB
    float s_[8], ss_[8];
#pragma unroll
    for (int k = 0; k < 8; k++) {
        int i = tid + k * THREADS;           // group(c) == k by construction
        int c = i >> 5, n4 = (i & 31) << 2;
        float4 v = *(const float4*)(x + ((size_t)b * C + c) * NTOK + n0 + n4);
        *(float4*)(Xs + c * 128 + n4) = v;
        s_[k]  = v.x + v.y + v.z + v.w;
        ss_[k] = v.x * v.x + v.y * v.y + v.z * v.z + v.w * v.w;
    }
#pragma unroll
    for (int k = 0; k < 8; k++)
#pragma unroll
        for (int o = 16; o > 0; o >>= 1) {
            s_[k]  += __shfl_xor_sync(0xffffffffu, s_[k], o);
            ss_[k] += __shfl_xor_sync(0xffffffffu, ss_[k], o);
        }
    __shared__ float2 wred[16][8];
    if (lane == 0)
#pragma unroll
        for (int k = 0; k < 8; k++) wred[w][k] = make_float2(s_[k], ss_[k]);
    __syncthreads();
    if (tid < 8) {
        float a = 0.f, bb = 0.f;
#pragma unroll
        for (int ww = 0; ww < 16; ww++) { a += wred[ww][tid].x; bb += wred[ww][tid].y; }
        g_part[(b * NG + tid) * 32 + blockIdx.x] = make_float2(a, bb);
    }
    __syncthreads();

    // global barrier A (32 CTAs of this batch)
    if (tid == 0) {
        asm volatile("red.release.gpu.global.add.u32 [%0], 1;"
                     :: "l"(&g_flag[b]) : "memory");
        unsigned v;
        do {
            asm volatile("ld.acquire.gpu.global.u32 %0, [%1];"
                         : "=r"(v) : "l"(&g_flag[b]) : "memory");
        } while (v < 32);
    }
    __syncthreads();

    __shared__ float stats[16];
    if (tid < 8) {
        float s = 0.f, ss = 0.f;
#pragma unroll
        for (int j = 0; j < 32; j++) {
            float2 p = g_part[(b * NG + tid) * 32 + j];
            s += p.x; ss += p.y;
        }
        float mean = s * (1.f / (CPG * NTOK));
        float var  = ss * (1.f / (CPG * NTOK)) - mean * mean;
        stats[tid * 2]     = mean;
        stats[tid * 2 + 1] = rsqrtf(var + EPS);
    }
    __syncthreads();

    // ============ PHASE 1: normalize (from smem) + QKV GEMM ============
    __nv_bfloat16* As = (__nv_bfloat16*)(sbc + WB_OFF);   // [c][m] pitch GP
    for (int i = tid; i < 128 * 32; i += THREADS) {
        int c = i >> 5, n4 = (i & 31) << 2;
        float4 v = *(const float4*)(Xs + c * 128 + n4);
        int g = c >> 4;
        float a = stats[g * 2 + 1] * gnw[c];
        float bb = gnb[c] - stats[g * 2] * a;
        *(uint32_t*)(As + c * GP + n4)     = pack_bf2(v.x * a + bb, v.y * a + bb);
        *(uint32_t*)(As + c * GP + n4 + 2) = pack_bf2(v.z * a + bb, v.w * a + bb);
    }
    __syncthreads();   // Xs reads done; stage region reusable for Bs

    const int l15 = lane & 15;
    const int hi8 = (lane >> 4) << 3;
    const int arow = (lane & 7) + ((lane >> 4) << 3);
    const int acol = ((lane >> 3) & 1) << 3;
    const uint32_t aA = sbase + WB_OFF + (arow * GP + wq * 16 + acol) * 2;
    __nv_bfloat16* Bs = (__nv_bfloat16*)(sbc + ST_OFF(0));
    const uint32_t aB = sbase + ST_OFF(0) + ((grp * 64 + l15) * GP + hi8) * 2;
    unsigned char* dstb = g_kv + (size_t)b * (64 * 32768);

    const int obs[3] = {1, 2, 0};            // K, V, Q (Q stays resident)
#pragma unroll 1
    for (int oi = 0; oi < 3; oi++) {
        const int ob = obs[oi];
        const int o0 = ob * 128;
        for (int i = tid; i < 128 * 32; i += THREADS) {
            int r = i >> 5, c4 = (i & 31) << 2;
            float4 v = *(const float4*)(W + (size_t)(o0 + r) * C + c4);
            *(uint32_t*)(Bs + r * GP + c4)     = pack_bf2(v.x, v.y);
            *(uint32_t*)(Bs + r * GP + c4 + 2) = pack_bf2(v.z, v.w);
        }
        __syncthreads();

        float acc[8][4];
#pragma unroll
        for (int i = 0; i < 8; i++)
#pragma unroll
            for (int j = 0; j < 4; j++) acc[i][j] = 0.f;

#pragma unroll
        for (int kk = 0; kk < 8; kk++) {
            const int k0 = kk * 16;
            uint32_t aq[4];
            LDSM4T(aq, aA + k0 * GP * 2);
#pragma unroll
            for (int ntp = 0; ntp < 4; ntp++) {
                uint32_t bk[4];
                LDSM4(bk, aB + (ntp * 16 * GP + k0) * 2);
                mma_bf16(acc[2 * ntp],     aq, bk[0], bk[2]);
                mma_bf16(acc[2 * ntp + 1], aq, bk[1], bk[3]);
            }
        }
        __syncthreads();

        const float sc = (ob == 0) ? QSCALE : 1.f;
#pragma unroll
        for (int nt = 0; nt < 8; nt++) {
            int o = grp * 64 + nt * 8 + 2 * tig;
            float b0 = bias[o0 + o], b1 = bias[o0 + o + 1];
            *(uint32_t*)(sb + qrow * QP + o) =
                pack_bf2((acc[nt][0] + b0) * sc, (acc[nt][1] + b1) * sc);
            *(uint32_t*)(sb + (qrow + 8) * QP + o) =
                pack_bf2((acc[nt][2] + b0) * sc, (acc[nt][3] + b1) * sc);
        }
        __syncthreads();

        if (ob != 0) {
            const int kv = ob - 1;
            for (int i = tid; i < 128 * 16; i += THREADS) {
                int r = i >> 4, ch = i & 15;
                int nl = n0 + r;
                int jt = nl >> 6, rl = nl & 63;
                int sub = ch >> 3;
                uint32_t off = (uint32_t)jt * 32768u + (uint32_t)kv * 16384u
                             + (uint32_t)sub * 8192u + (uint32_t)rl * 128u
                             + ((((uint32_t)rl & 7u) * 16u) ^ (((uint32_t)ch & 7u) * 16u));
                *(uint4*)(dstb + off) = *(const uint4*)(sb + r * QP + ch * 8);
            }
            __syncthreads();
        }
    }

    // W_proj into WB (As retired); init full[3] + free[3] mbarriers
    __nv_bfloat16* Ws = (__nv_bfloat16*)(sbc + WB_OFF);
    for (int i = tid; i < 128 * 32; i += THREADS) {
        int r = i >> 5, c4 = (i & 31) << 2;
        float4 v = *(const float4*)(pw + (size_t)r * C + c4);
        *(uint32_t*)(Ws + r * GP + c4)     = pack_bf2(v.x, v.y);
        *(uint32_t*)(Ws + r * GP + c4 + 2) = pack_bf2(v.z, v.w);
    }
    if (tid == 0) {
        MBAR_INIT(mbar + 0, 1);    // full[0..2]
        MBAR_INIT(mbar + 8, 1);
        MBAR_INIT(mbar + 16, 1);
        MBAR_INIT(mbar + 24, 16);  // free[0..2]: one arrive per warp
        MBAR_INIT(mbar + 32, 16);
        MBAR_INIT(mbar + 40, 16);
    }
    __syncthreads();

    // ============ global barrier B (32 CTAs of this batch) ============
    if (tid == 0) {
        asm volatile("red.release.gpu.global.add.u32 [%0], 1;"
                     :: "l"(&g_flag[4 + b]) : "memory");
        unsigned v;
        do {
            asm volatile("ld.acquire.gpu.global.u32 %0, [%1];"
                         : "=r"(v) : "l"(&g_flag[4 + b]) : "memory");
        } while (v < 32);
    }
    __syncthreads();
    asm volatile("fence.proxy.async;" ::: "memory");

    // ============ PHASE 2: decoupled-pipeline flash attention ============
    const unsigned char* KVg = dstb;
    if (tid == 0) {
        MBAR_EXPECT_TX(mbar + 0, STB);
        bulkcp(sbase + ST_OFF(0), KVg, STB, mbar + 0);
        MBAR_EXPECT_TX(mbar + 8, STB);
        bulkcp(sbase + ST_OFF(1), KVg + STB, STB, mbar + 8);
    }

    const uint32_t aQ = sbase + ((wq * 16 + l15) * QP + hi8) * 2;
    const int vrow = (lane & 7) + ((lane >> 3) & 1) * 8;

    float oacc[16][4];
#pragma unroll
    for (int i = 0; i < 16; i++)
#pragma unroll
        for (int j = 0; j < 4; j++) oacc[i][j] = 0.f;
    float l0 = 0.f, l1 = 0.f;

    const int NT = NTOK / TKEY;
    for (int jt = 0; jt < NT; jt++) {
        const int s = jt % 3;
        // prefetch tile jt+2 (thread 0 only; waits on free[s2])
        if (jt + 2 < NT && tid == 0) {
            const int T = jt + 2, s2 = T % 3, f = T / 3;
            if (f >= 1) MBAR_WAIT(mbar + 24 + 8 * s2, (f - 1) & 1);
            MBAR_EXPECT_TX(mbar + 8 * s2, STB);
            bulkcp(sbase + ST_OFF(s2), KVg + (size_t)T * STB, STB, mbar + 8 * s2);
        }
        MBAR_WAIT(mbar + 8 * s, (jt / 3) & 1);   // per-warp full wait; no CTA sync

        const uint32_t stK = sbase + ST_OFF(s);
        const uint32_t stV = stK + 16384;

        // ---- S = Q K^T for this warp's 32-key half ----
        float sacc[4][4];
#pragma unroll
        for (int i = 0; i < 4; i++)
#pragma unroll
            for (int j = 0; j < 4; j++) sacc[i][j] = 0.f;

#pragma unroll
        for (int kk = 0; kk < 8; kk++) {
            const int k0 = kk * 16;
            uint32_t aq[4];
            LDSM4(aq, aQ + k0 * 2);
            const uint32_t sub = (k0 >= 64) ? 8192u : 0u;
            const uint32_t colb = (uint32_t)(((k0 & 63) + hi8) * 2);
#pragma unroll
            for (int ntp = 0; ntp < 2; ntp++) {
                const uint32_t row = (uint32_t)(kh + ntp * 16 + l15);
                uint32_t bk[4];
                LDSM4(bk, stK + sub + row * 128u + (((row & 7u) * 16u) ^ colb));
                mma_bf16(sacc[2 * ntp],     aq, bk[0], bk[2]);
                mma_bf16(sacc[2 * ntp + 1], aq, bk[1], bk[3]);
            }
        }

        // ---- softmax (ex2) + O-MMA over the 32-key half ----
#pragma unroll
        for (int kk = 0; kk < 2; kk++) {
            uint32_t ap[4];
            {
                float p0 = ex2f(sacc[2 * kk][0]);
                float p1 = ex2f(sacc[2 * kk][1]);
                float p2 = ex2f(sacc[2 * kk][2]);
                float p3 = ex2f(sacc[2 * kk][3]);
                l0 += p0 + p1; l1 += p2 + p3;
                ap[0] = pack_bf2(p0, p1);
                ap[1] = pack_bf2(p2, p3);
                float q0 = ex2f(sacc[2 * kk + 1][0]);
                float q1 = ex2f(sacc[2 * kk + 1][1]);
                float q2 = ex2f(sacc[2 * kk + 1][2]);
                float q3 = ex2f(sacc[2 * kk + 1][3]);
                l0 += q0 + q1; l1 += q2 + q3;
                ap[2] = pack_bf2(q0, q1);
                ap[3] = pack_bf2(q2, q3);
            }
            const uint32_t rowb = (uint32_t)(kh + kk * 16 + vrow);
            const uint32_t rxor = (rowb & 7u) * 16u;
#pragma unroll
            for (int ccp = 0; ccp < 8; ccp++) {
                const int cc = ccp * 16 + hi8;
                const uint32_t sub = (cc >= 64) ? 8192u : 0u;
                const uint32_t colb = (uint32_t)((cc & 63) * 2);
                uint32_t bv[4];
                LDSM4T(bv, stV + sub + rowb * 128u + (rxor ^ colb));
                mma_bf16(oacc[2 * ccp],     ap, bv[0], bv[1]);
                mma_bf16(oacc[2 * ccp + 1], ap, bv[2], bv[3]);
            }
        }
        if (lane == 0) MBAR_ARRIVE(mbar + 24 + 8 * s);   // this warp done with stage
    }
    __syncthreads();   // all warps done; stage regions reusable

    // ---- merge key-halves: quad-reduce l, grp0 dumps ----
    l0 += __shfl_xor_sync(0xffffffffu, l0, 1);
    l0 += __shfl_xor_sync(0xffffffffu, l0, 2);
    l1 += __shfl_xor_sync(0xffffffffu, l1, 1);
    l1 += __shfl_xor_sync(0xffffffffu, l1, 2);

    float* Om   = (float*)(sbc + ST_OFF(0));   // [q:128][c:128] pitch OMP
    float* lsum = (float*)(sbc + LS_OFF);
    if (grp == 0) {
#pragma unroll
        for (int nt = 0; nt < 16; nt++) {
            int col = nt * 8 + 2 * tig;
            Om[qrow * OMP + col]           = oacc[nt][0];
            Om[qrow * OMP + col + 1]       = oacc[nt][1];
            Om[(qrow + 8) * OMP + col]     = oacc[nt][2];
            Om[(qrow + 8) * OMP + col + 1] = oacc[nt][3];
        }
        if (tig == 0) { lsum[qrow] = l0; lsum[qrow + 8] = l1; }
    }
    __syncthreads();

    if (grp == 1) {
        float inv0 = 1.f / (l0 + lsum[qrow]);
        float inv1 = 1.f / (l1 + lsum[qrow + 8]);
#pragma unroll
        for (int nt = 0; nt < 16; nt++) {
            int col = nt * 8 + 2 * tig;
            float o0 = (Om[qrow * OMP + col]           + oacc[nt][0]) * inv0;
            float o1 = (Om[qrow * OMP + col + 1]       + oacc[nt][1]) * inv0;
            float o2 = (Om[(qrow + 8) * OMP + col]     + oacc[nt][2]) * inv1;
            float o3 = (Om[(qrow + 8) * OMP + col + 1] + oacc[nt][3]) * inv1;
            *(uint32_t*)(sb + qrow * QP + col)       = pack_bf2(o0, o1);
            *(uint32_t*)(sb + (qrow + 8) * QP + col) = pack_bf2(o2, o3);
        }
    }
    __syncthreads();

    // ---- fused proj: warp does 16q x 64o ----
    const uint32_t aW = sbase + WB_OFF + ((grp * 64 + l15) * GP + hi8) * 2;

    float acc[8][4];
#pragma unroll
    for (int i = 0; i < 8; i++)
#pragma unroll
        for (int j = 0; j < 4; j++) acc[i][j] = 0.f;

#pragma unroll
    for (int kk = 0; kk < 8; kk++) {
        const int k0 = kk * 16;
        uint32_t aq[4];
        LDSM4(aq, aQ + k0 * 2);            // O lives in Q region
#pragma unroll
        for (int ntp = 0; ntp < 4; ntp++) {
            uint32_t bk[4];
            LDSM4(bk, aW + (ntp * 16 * GP + k0) * 2);
            mma_bf16(acc[2 * ntp],     aq, bk[0], bk[2]);
            mma_bf16(acc[2 * ntp + 1], aq, bk[1], bk[3]);
        }
    }
    __syncthreads();   // Om reads done; stage region reusable

    // ---- stage proj fp32 [o:128][n:128] pitch OMP ----
    float* Pf = (float*)(sbc + ST_OFF(0));
    const int nl = wq * 16 + gid;
#pragma unroll
    for (int nt = 0; nt < 8; nt++) {
        int o = grp * 64 + nt * 8 + 2 * tig;
        Pf[o * OMP + nl]           = acc[nt][0];
        Pf[(o + 1) * OMP + nl]     = acc[nt][1];
        Pf[o * OMP + nl + 8]       = acc[nt][2];
        Pf[(o + 1) * OMP + nl + 8] = acc[nt][3];
    }
    __syncthreads();

    // ---- coalesced residual add + store ----
    for (int i = tid; i < 128 * 32; i += THREADS) {
        int o = i >> 5, n4 = (i & 31) << 2;
        size_t gaddr = ((size_t)b * C + o) * NTOK + n0 + n4;
        float4 xv = *(const float4*)(x + gaddr);
        float4 ov = *(const float4*)(Pf + o * OMP + n4);
        float bo = pb[o];
        float4 r = make_float4(xv.x + ov.x + bo, xv.y + ov.y + bo,
                               xv.z + ov.z + bo, xv.w + ov.w + bo);
        *(float4*)(y + gaddr) = r;
    }
}

// ---------------------------------------------------------------------------
extern "C" void kernel_launch(void* const* d_in, const int* in_sizes, int n_in,
                              void* d_out, int out_size)
{
    const float* x     = (const float*)d_in[0];
    const float* gn_w  = (const float*)d_in[1];
    const float* gn_b  = (const float*)d_in[2];
    const float* qkv_w = (const float*)d_in[3];
    const float* qkv_b = (const float*)d_in[4];
    const float* pr_w  = (const float*)d_in[5];
    const float* pr_b  = (const float*)d_in[6];
    float* y = (float*)d_out;

    cudaFuncSetAttribute(mega_kernel, cudaFuncAttributeMaxDynamicSharedMemorySize,
                         MEGA_SMEM);

    void* flagptr = nullptr;
    cudaGetSymbolAddress(&flagptr, g_flag);
    cudaMemsetAsync(flagptr, 0, 8 * sizeof(unsigned int));

    mega_kernel<<<dim3(NTOK / TQ, BATCH), THREADS, MEGA_SMEM>>>(
        x, gn_w, gn_b, qkv_w, qkv_b, pr_w, pr_b, y);
}